// round 5
// baseline (speedup 1.0000x reference)
#include <cuda_runtime.h>
#include <math.h>

#define BS_    64
#define KK_    4
#define PTS_   5
#define RES_   28
#define STEPS_ 500
#define THALF_ 250      // t-range per CTA
#define TC_    125      // t-chunk size within CTA
#define NCHUNK_ 2
#define NT_    256
#define NG_    4        // t-groups per CTA
#define PIX_ (RES_*RES_)   // 784

typedef unsigned long long u64;

// cross-CTA staging
__device__ float g_part[2 * BS_ * KK_ * PIX_];   // per half-CTA partial strokes
__device__ float g_stage[BS_ * KK_ * PIX_];      // tanh-normed strokes per (b,k)
__device__ unsigned int g_cnt2[BS_ * KK_];       // pair counters (zero-init)
__device__ unsigned int g_cnt[BS_];              // batch counters (zero-init)

__device__ __forceinline__ void fma2(u64 &d, u64 a, u64 b) {
    asm("fma.rn.f32x2 %0, %1, %2, %3;" : "=l"(d) : "l"(a), "l"(b), "l"(d));
}
__device__ __forceinline__ void unpack2(u64 v, float &lo, float &hi) {
    asm("mov.b64 {%0,%1}, %2;" : "=f"(lo), "=f"(hi) : "l"(v));
}

__global__ __launch_bounds__(NT_, 4)
void guide_fused_kernel(const float* __restrict__ z_pres,
                        const float* __restrict__ z_what,
                        const float* __restrict__ z_where,
                        const float* __restrict__ sigma_p,
                        const float* __restrict__ slope_strk_p,
                        const float* __restrict__ slope_p,
                        float* __restrict__ out)
{
    // Ex: TC_*28 floats (14000B) | Eyd: TC_*56 floats dup pairs (28000B) = 42KB
    // part (NG_*784 = 12.5KB) aliases after the accumulation loop.
    __shared__ float sh[TC_ * RES_ + TC_ * 2 * RES_];
    __shared__ float red[8];
    __shared__ unsigned int flags;   // bit0: pair-last, bit1: batch-last

    float* Ex  = sh;
    float* Eyd = sh + TC_ * RES_;

    const int bid  = blockIdx.x;          // 0..511
    const int bk   = bid >> 1;            // 0..255 = b*4 + k
    const int half = bid & 1;             // t-half
    const int tid  = threadIdx.x;

    // ---- transform params (uniform) ----
    const float s   = z_where[bk * 3 + 0];
    const float sh0 = z_where[bk * 3 + 1];
    const float sh1 = z_where[bk * 3 + 2];

    float px0, px1, px2, px3, px4, py0, py1, py2, py3, py4;
    {
        const float* w = z_what + bk * PTS_ * 2;
        px0 = w[0] * s + sh0;  py0 = w[1] * s + sh1;
        px1 = w[2] * s + sh0;  py1 = w[3] * s + sh1;
        px2 = w[4] * s + sh0;  py2 = w[5] * s + sh1;
        px3 = w[6] * s + sh0;  py3 = w[7] * s + sh1;
        px4 = w[8] * s + sh0;  py4 = w[9] * s + sh1;
    }
    const float sigma = *sigma_p;
    const float ninv  = -1.0f / (2.0f * sigma * sigma);

    // phase-2 mapping: 4 t-groups x 64 threads (49 active: 7x7 tiles of 4x4 px)
    const int g   = tid >> 6;     // 0..3
    const int sid = tid & 63;
    const int ty  = sid / 7;
    const int tx  = sid - ty * 7;
    const bool act = (sid < 49);

    u64 acc[4][2];
#pragma unroll
    for (int i = 0; i < 4; i++) { acc[i][0] = 0ull; acc[i][1] = 0ull; }

#pragma unroll
    for (int c = 0; c < NCHUNK_; c++) {
        const int t0 = half * THALF_ + c * TC_;
        __syncthreads();   // previous chunk fully consumed before overwrite

        // ---- phase 1: fill Ex (plain) / Eyd (dup pairs); 250 tasks / 256 thr ----
        if (tid < 2 * TC_) {
            const int tr  = tid >> 1;
            const int isY = tid & 1;
            const float u  = (float)(t0 + tr) * (1.0f / (float)(STEPS_ - 1));
            const float v  = 1.0f - u;
            const float u2 = u * u, v2 = v * v;
            const float b0 = v2 * v2;
            const float b1 = 4.0f * u * (v * v2);
            const float b2 = 6.0f * u2 * v2;
            const float b3 = 4.0f * (u2 * u) * v;
            const float b4 = u2 * u2;
            const float cx = b0*px0 + b1*px1 + b2*px2 + b3*px3 + b4*px4;
            const float cy = b0*py0 + b1*py1 + b2*py2 + b3*py3 + b4*py4;
            if (!isY) {
                const float cc = cx;
                float4* row4 = (float4*)(Ex + tr * RES_);
#pragma unroll
                for (int q = 0; q < 7; q++) {
                    float4 r;
                    float d0 = (float)(4*q + 0) * (1.0f/27.0f) - cc;
                    float d1 = (float)(4*q + 1) * (1.0f/27.0f) - cc;
                    float d2 = (float)(4*q + 2) * (1.0f/27.0f) - cc;
                    float d3 = (float)(4*q + 3) * (1.0f/27.0f) - cc;
                    r.x = __expf(d0 * d0 * ninv);
                    r.y = __expf(d1 * d1 * ninv);
                    r.z = __expf(d2 * d2 * ninv);
                    r.w = __expf(d3 * d3 * ninv);
                    row4[q] = r;
                }
            } else {
                const float cc = cy;
                float4* row4 = (float4*)(Eyd + tr * 2 * RES_);
#pragma unroll
                for (int q = 0; q < 14; q++) {
                    float d0 = (float)(2*q + 0) * (1.0f/27.0f) - cc;
                    float d1 = (float)(2*q + 1) * (1.0f/27.0f) - cc;
                    float e0 = __expf(d0 * d0 * ninv);
                    float e1 = __expf(d1 * d1 * ninv);
                    float4 r; r.x = e0; r.y = e0; r.z = e1; r.w = e1;
                    row4[q] = r;
                }
            }
        }
        __syncthreads();

        // ---- phase 2: rank-1 accumulation, all operands packed from LDS ----
        if (act) {
            const int tl0 = (TC_ * g) >> 2;
            const int tl1 = (TC_ * (g + 1)) >> 2;
            const float* exp_ = Ex  + tl0 * RES_ + (tx << 2);
            const float* eyp_ = Eyd + tl0 * 2 * RES_ + (ty << 3);
            int n = tl1 - tl0;
#pragma unroll 1
            for (; n >= 2; n -= 2) {
                const ulonglong2 ex0 = *(const ulonglong2*)(exp_);
                const ulonglong2 ya0 = *(const ulonglong2*)(eyp_);
                const ulonglong2 yb0 = *(const ulonglong2*)(eyp_ + 4);
                const ulonglong2 ex1 = *(const ulonglong2*)(exp_ + RES_);
                const ulonglong2 ya1 = *(const ulonglong2*)(eyp_ + 2 * RES_);
                const ulonglong2 yb1 = *(const ulonglong2*)(eyp_ + 2 * RES_ + 4);
                exp_ += 2 * RES_; eyp_ += 4 * RES_;
                fma2(acc[0][0], ya0.x, ex0.x); fma2(acc[0][1], ya0.x, ex0.y);
                fma2(acc[1][0], ya0.y, ex0.x); fma2(acc[1][1], ya0.y, ex0.y);
                fma2(acc[2][0], yb0.x, ex0.x); fma2(acc[2][1], yb0.x, ex0.y);
                fma2(acc[3][0], yb0.y, ex0.x); fma2(acc[3][1], yb0.y, ex0.y);
                fma2(acc[0][0], ya1.x, ex1.x); fma2(acc[0][1], ya1.x, ex1.y);
                fma2(acc[1][0], ya1.y, ex1.x); fma2(acc[1][1], ya1.y, ex1.y);
                fma2(acc[2][0], yb1.x, ex1.x); fma2(acc[2][1], yb1.x, ex1.y);
                fma2(acc[3][0], yb1.y, ex1.x); fma2(acc[3][1], yb1.y, ex1.y);
            }
            if (n) {
                const ulonglong2 ex0 = *(const ulonglong2*)(exp_);
                const ulonglong2 ya0 = *(const ulonglong2*)(eyp_);
                const ulonglong2 yb0 = *(const ulonglong2*)(eyp_ + 4);
                fma2(acc[0][0], ya0.x, ex0.x); fma2(acc[0][1], ya0.x, ex0.y);
                fma2(acc[1][0], ya0.y, ex0.x); fma2(acc[1][1], ya0.y, ex0.y);
                fma2(acc[2][0], yb0.x, ex0.x); fma2(acc[2][1], yb0.x, ex0.y);
                fma2(acc[3][0], yb0.y, ex0.x); fma2(acc[3][1], yb0.y, ex0.y);
            }
        }
    }
    __syncthreads();

    // ---- merge NG_ t-group partials (part aliases sh) ----
    float* part = sh;
    if (act) {
        float* pbase = part + g * PIX_;
#pragma unroll
        for (int i = 0; i < 4; i++) {
            float v0, v1, v2, v3;
            unpack2(acc[i][0], v0, v1);
            unpack2(acc[i][1], v2, v3);
            float* row = pbase + (ty * 4 + i) * RES_ + (tx * 4);
            row[0] = v0; row[1] = v1; row[2] = v2; row[3] = v3;
        }
    }
    __syncthreads();

    // ---- write this half-CTA's partial strokes to global ----
    float* gp = g_part + bid * PIX_;
#pragma unroll
    for (int r = 0; r < 4; r++) {
        const int p = r * NT_ + tid;
        if (p < PIX_)
            gp[p] = part[p] + part[PIX_ + p] + part[2*PIX_ + p] + part[3*PIX_ + p];
    }

    // ---- pair sync: last of the 2 half-CTAs finishes the stroke ----
    if (tid == 0) {
        __threadfence();
        unsigned int old = atomicAdd(&g_cnt2[bk], 1u);
        flags = (old == 1u) ? 1u : 0u;
    }
    __syncthreads();
    if (!(flags & 1u)) return;

    __threadfence();   // acquire partner's g_part writes
    const float* gp0 = g_part + (bk * 2 + 0) * PIX_;
    const float* gp1 = g_part + (bk * 2 + 1) * PIX_;
    const float zp = z_pres[bk];
    float myv[4];
    float lmax = 0.0f;
#pragma unroll
    for (int r = 0; r < 4; r++) {
        const int p = r * NT_ + tid;
        float v = 0.0f;
        if (p < PIX_) v = (gp0[p] + gp1[p]) * zp;
        myv[r] = v;
        lmax = fmaxf(lmax, v);
    }
#pragma unroll
    for (int o = 16; o > 0; o >>= 1)
        lmax = fmaxf(lmax, __shfl_xor_sync(0xffffffffu, lmax, o));
    if ((tid & 31) == 0) red[tid >> 5] = lmax;
    __syncthreads();
    float bmax = red[0];
#pragma unroll
    for (int w = 1; w < 8; w++) bmax = fmaxf(bmax, red[w]);

    const float scale = 1.0f / (bmax + 1e-6f);
    const float sl    = *slope_strk_p;
    const float itsl  = 1.0f / tanhf(sl);
    float* stage = g_stage + bk * PIX_;
#pragma unroll
    for (int r = 0; r < 4; r++) {
        const int p = r * NT_ + tid;
        if (p < PIX_)
            stage[p] = tanhf(myv[r] * scale * sl) * itsl;
    }
    if (tid == 0) g_cnt2[bk] = 0u;   // reset pair counter for next replay

    // ---- batch sync: last of 4 stroke-finishers composes the image ----
    if (tid == 0) {
        __threadfence();
        unsigned int old = atomicAdd(&g_cnt[bk >> 2], 1u);
        flags = (old == 3u) ? 2u : 0u;
    }
    __syncthreads();
    if (!(flags & 2u)) return;

    __threadfence();   // acquire peers' stage writes
    const int b = bk >> 2;
    const float* st = g_stage + b * KK_ * PIX_;
    const float sl2 = *slope_p;
    const float it2 = 1.0f / tanhf(sl2);
    for (int p = tid; p < PIX_; p += NT_) {
        const float ssum = st[p] + st[PIX_ + p] + st[2*PIX_ + p] + st[3*PIX_ + p];
        out[b * PIX_ + p] = tanhf(ssum * sl2) * it2;
    }
    if (tid == 0) g_cnt[b] = 0u;     // reset batch counter for next replay
}

extern "C" void kernel_launch(void* const* d_in, const int* in_sizes, int n_in,
                              void* d_out, int out_size)
{
    const float* z_pres     = (const float*)d_in[0];
    const float* z_what     = (const float*)d_in[1];
    const float* z_where    = (const float*)d_in[2];
    const float* sigma      = (const float*)d_in[3];
    const float* slope_strk = (const float*)d_in[4];
    const float* slope      = (const float*)d_in[5];
    float* out = (float*)d_out;

    guide_fused_kernel<<<2 * BS_ * KK_, NT_>>>(z_pres, z_what, z_where,
                                               sigma, slope_strk, slope, out);
}

// round 6
// speedup vs baseline: 1.3183x; 1.3183x over previous
#include <cuda_runtime.h>
#include <math.h>

#define BS_    64
#define KK_    4
#define PTS_   5
#define RES_   28
#define STEPS_ 500
#define TC_    125      // t-chunk size
#define NCHUNK_ 4
#define NT_    512
#define NG_    8        // t-groups
#define PIX_ (RES_*RES_)   // 784
#define BUFF_ (2 * TC_ * RES_)                    // floats per buffer (7000)
#define SMEM_BYTES_ (2 * BUFF_ * sizeof(float))   // 56000

typedef unsigned long long u64;

// staging: tanh-normed strokes per (b,k)
__device__ float g_stage[BS_ * KK_ * PIX_];
// per-batch arrival counters for fused compose (zero-init; reset each run)
__device__ unsigned int g_cnt[BS_];

__device__ __forceinline__ void fma2(u64 &d, u64 a, u64 b) {
    asm("fma.rn.f32x2 %0, %1, %2, %3;" : "=l"(d) : "l"(a), "l"(b), "l"(d));
}
__device__ __forceinline__ u64 pack2(float v) {
    u64 r; asm("mov.b64 %0, {%1,%1};" : "=l"(r) : "f"(v)); return r;
}
__device__ __forceinline__ void unpack2(u64 v, float &lo, float &hi) {
    asm("mov.b64 {%0,%1}, %2;" : "=f"(lo), "=f"(hi) : "l"(v));
}

__global__ __launch_bounds__(NT_, 2)
void guide_fused_kernel(const float* __restrict__ z_pres,
                        const float* __restrict__ z_what,
                        const float* __restrict__ z_where,
                        const float* __restrict__ sigma_p,
                        const float* __restrict__ slope_strk_p,
                        const float* __restrict__ slope_p,
                        float* __restrict__ out)
{
    extern __shared__ float sh[];   // 2 buffers of [Ex TC_*28 | Ey TC_*28]
    __shared__ float red[16];
    __shared__ unsigned int slast;

    const int bk  = blockIdx.x;           // 0..255 = b*4 + k
    const int tid = threadIdx.x;

    // ---- transform params (uniform) ----
    const float s   = z_where[bk * 3 + 0];
    const float sh0 = z_where[bk * 3 + 1];
    const float sh1 = z_where[bk * 3 + 2];

    float px0, px1, px2, px3, px4, py0, py1, py2, py3, py4;
    {
        const float* w = z_what + bk * PTS_ * 2;
        px0 = w[0] * s + sh0;  py0 = w[1] * s + sh1;
        px1 = w[2] * s + sh0;  py1 = w[3] * s + sh1;
        px2 = w[4] * s + sh0;  py2 = w[5] * s + sh1;
        px3 = w[6] * s + sh0;  py3 = w[7] * s + sh1;
        px4 = w[8] * s + sh0;  py4 = w[9] * s + sh1;
    }
    const float sigma = *sigma_p;
    const float ninv  = -1.0f / (2.0f * sigma * sigma);

    // phase-1 mapping: warp-uniform q-halves.
    // warps 0-7 (tid<256): q in [0,4); warps 8-15: q in [4,7).
    const int qh  = tid >> 8;          // 0 or 1
    const int rt  = tid & 255;         // row-task, valid if < 2*TC_
    const int p1tr  = rt >> 1;
    const int p1isY = rt & 1;
    const int q0 = qh << 2;            // 0 or 4
    const int q1 = qh ? 7 : 4;

    // phase-2 mapping: 8 t-groups x 64 threads (49 active: 7x7 tiles of 4x4 px)
    const int g   = tid >> 6;
    const int sid = tid & 63;
    const int ty  = sid / 7;
    const int tx  = sid - ty * 7;
    const bool act = (sid < 49);
    const int tl0 = (TC_ * g) >> 3;
    const int tl1 = (TC_ * (g + 1)) >> 3;

    u64 acc[4][2];
#pragma unroll
    for (int i = 0; i < 4; i++) { acc[i][0] = 0ull; acc[i][1] = 0ull; }

    // ---- phase 1 body as a lambda over (chunk t0, buffer base) ----
    auto phase1 = [&](int t0, float* buf) {
        if (rt < 2 * TC_) {
            const float u  = (float)(t0 + p1tr) * (1.0f / (float)(STEPS_ - 1));
            const float v  = 1.0f - u;
            const float u2 = u * u, v2 = v * v;
            const float b0 = v2 * v2;
            const float b1 = 4.0f * u * (v * v2);
            const float b2 = 6.0f * u2 * v2;
            const float b3 = 4.0f * (u2 * u) * v;
            const float b4 = u2 * u2;
            const float cx = b0*px0 + b1*px1 + b2*px2 + b3*px3 + b4*px4;
            const float cy = b0*py0 + b1*py1 + b2*py2 + b3*py3 + b4*py4;
            const float cc = p1isY ? cy : cx;
            float4* row4 = (float4*)(buf + p1isY * (TC_ * RES_) + p1tr * RES_);
            for (int q = q0; q < q1; q++) {
                float4 r;
                float d0 = (float)(4*q + 0) * (1.0f/27.0f) - cc;
                float d1 = (float)(4*q + 1) * (1.0f/27.0f) - cc;
                float d2 = (float)(4*q + 2) * (1.0f/27.0f) - cc;
                float d3 = (float)(4*q + 3) * (1.0f/27.0f) - cc;
                r.x = __expf(d0 * d0 * ninv);
                r.y = __expf(d1 * d1 * ninv);
                r.z = __expf(d2 * d2 * ninv);
                r.w = __expf(d3 * d3 * ninv);
                row4[q] = r;
            }
        }
    };

    // ---- prologue: fill buffer 0 with chunk 0 ----
    phase1(0, sh);
    __syncthreads();

    // ---- main loop: overlap phase1(c+1 -> other buf) with phase2(c) ----
#pragma unroll
    for (int c = 0; c < NCHUNK_; c++) {
        float* cur = sh + (c & 1) * BUFF_;
        if (c + 1 < NCHUNK_)
            phase1((c + 1) * TC_, sh + ((c + 1) & 1) * BUFF_);

        if (act) {
            const float* ep = cur + tl0 * RES_ + (tx << 2);
            const float* yp = cur + TC_ * RES_ + tl0 * RES_ + (ty << 2);
            int n = tl1 - tl0;
            float4 exA = *(const float4*)ep;
            float4 eyA = *(const float4*)yp;
#pragma unroll 2
            for (; n > 1; n--) {
                ep += RES_; yp += RES_;
                const float4 exB = *(const float4*)ep;   // prefetch next
                const float4 eyB = *(const float4*)yp;
                {
                    const u64 a0 = pack2(eyA.x), a1 = pack2(eyA.y);
                    const u64 a2 = pack2(eyA.z), a3 = pack2(eyA.w);
                    const u64 xlo = *(const u64*)&exA.x;
                    const u64 xhi = *(const u64*)&exA.z;
                    fma2(acc[0][0], a0, xlo); fma2(acc[0][1], a0, xhi);
                    fma2(acc[1][0], a1, xlo); fma2(acc[1][1], a1, xhi);
                    fma2(acc[2][0], a2, xlo); fma2(acc[2][1], a2, xhi);
                    fma2(acc[3][0], a3, xlo); fma2(acc[3][1], a3, xhi);
                }
                exA = exB; eyA = eyB;
            }
            {
                const u64 a0 = pack2(eyA.x), a1 = pack2(eyA.y);
                const u64 a2 = pack2(eyA.z), a3 = pack2(eyA.w);
                const u64 xlo = *(const u64*)&exA.x;
                const u64 xhi = *(const u64*)&exA.z;
                fma2(acc[0][0], a0, xlo); fma2(acc[0][1], a0, xhi);
                fma2(acc[1][0], a1, xlo); fma2(acc[1][1], a1, xhi);
                fma2(acc[2][0], a2, xlo); fma2(acc[2][1], a2, xhi);
                fma2(acc[3][0], a3, xlo); fma2(acc[3][1], a3, xhi);
            }
        }
        __syncthreads();
    }

    // ---- merge 8 t-group partials (part aliases buffer 0; free now) ----
    float* part = sh;
    if (act) {
        float* pbase = part + g * PIX_;
#pragma unroll
        for (int i = 0; i < 4; i++) {
            float v0, v1, v2, v3;
            unpack2(acc[i][0], v0, v1);
            unpack2(acc[i][1], v2, v3);
            float* row = pbase + (ty * 4 + i) * RES_ + (tx * 4);
            row[0] = v0; row[1] = v1; row[2] = v2; row[3] = v3;
        }
    }
    __syncthreads();

    // ---- epilogue: z_pres scale, maxnorm, tanh-norm, stage ----
    const float zp = z_pres[bk];
    float myv[2];
    float lmax = 0.0f;
#pragma unroll
    for (int r = 0; r < 2; r++) {
        const int p = r * NT_ + tid;
        float v = 0.0f;
        if (p < PIX_) {
            v = part[p];
#pragma unroll
            for (int gg = 1; gg < NG_; gg++) v += part[gg * PIX_ + p];
            v *= zp;
        }
        myv[r] = v;
        lmax = fmaxf(lmax, v);
    }
#pragma unroll
    for (int o = 16; o > 0; o >>= 1)
        lmax = fmaxf(lmax, __shfl_xor_sync(0xffffffffu, lmax, o));
    if ((tid & 31) == 0) red[tid >> 5] = lmax;
    __syncthreads();
    float bmax = red[0];
#pragma unroll
    for (int w = 1; w < 16; w++) bmax = fmaxf(bmax, red[w]);

    const float scale = 1.0f / (bmax + 1e-6f);
    const float sl    = *slope_strk_p;
    const float itsl  = 1.0f / tanhf(sl);
    float* stage = g_stage + bk * PIX_;
#pragma unroll
    for (int r = 0; r < 2; r++) {
        const int p = r * NT_ + tid;
        if (p < PIX_)
            stage[p] = tanhf(myv[r] * scale * sl) * itsl;
    }

    // ---- fused compose: last CTA of each batch composes the image ----
    if (tid == 0) {
        __threadfence();   // publish stage writes before arrival
        unsigned int old = atomicAdd(&g_cnt[bk >> 2], 1u);
        slast = (old == 3u) ? 1u : 0u;
    }
    __syncthreads();
    if (slast) {
        __threadfence();   // acquire: see peer CTAs' stage writes
        const int b = bk >> 2;
        const float* st = g_stage + b * KK_ * PIX_;
        const float sl2 = *slope_p;
        const float it2 = 1.0f / tanhf(sl2);
        for (int p = tid; p < PIX_; p += NT_) {
            const float ssum = st[p] + st[PIX_ + p] + st[2*PIX_ + p] + st[3*PIX_ + p];
            out[b * PIX_ + p] = tanhf(ssum * sl2) * it2;
        }
        if (tid == 0) g_cnt[b] = 0u;   // reset for next (graph-replayed) call
    }
}

extern "C" void kernel_launch(void* const* d_in, const int* in_sizes, int n_in,
                              void* d_out, int out_size)
{
    const float* z_pres     = (const float*)d_in[0];
    const float* z_what     = (const float*)d_in[1];
    const float* z_where    = (const float*)d_in[2];
    const float* sigma      = (const float*)d_in[3];
    const float* slope_strk = (const float*)d_in[4];
    const float* slope      = (const float*)d_in[5];
    float* out = (float*)d_out;

    cudaFuncSetAttribute(guide_fused_kernel,
                         cudaFuncAttributeMaxDynamicSharedMemorySize,
                         (int)SMEM_BYTES_);
    guide_fused_kernel<<<BS_ * KK_, NT_, SMEM_BYTES_>>>(z_pres, z_what, z_where,
                                                        sigma, slope_strk, slope, out);
}

// round 7
// speedup vs baseline: 1.6336x; 1.2393x over previous
#include <cuda_runtime.h>
#include <math.h>

#define BS_    64
#define KK_    4
#define PTS_   5
#define RES_   28
#define STEPS_ 500
#define NT_    256
#define NW_    8            // warps per CTA
#define KSTEPS_ 63          // ceil(504/8)
#define KPAD_  504
#define PIX_ (RES_*RES_)    // 784
#define PSTR_ 34            // padded row stride of C partial
#define PWARP_ (32*PSTR_)   // 1088 floats per warp partial

// staging: tanh-normed strokes per (b,k)
__device__ float g_stage[BS_ * KK_ * PIX_];
// per-batch arrival counters for fused compose (zero-init; reset each run)
__device__ unsigned int g_cnt[BS_];

__device__ __forceinline__ void mma_tf32(float* d,
                                         unsigned a0, unsigned a1, unsigned a2, unsigned a3,
                                         unsigned b0, unsigned b1) {
    asm volatile(
        "mma.sync.aligned.m16n8k8.row.col.f32.tf32.tf32.f32 "
        "{%0,%1,%2,%3}, {%4,%5,%6,%7}, {%8,%9}, {%0,%1,%2,%3};"
        : "+f"(d[0]), "+f"(d[1]), "+f"(d[2]), "+f"(d[3])
        : "r"(a0), "r"(a1), "r"(a2), "r"(a3), "r"(b0), "r"(b1));
}
__device__ __forceinline__ unsigned tf32_big(float v) {
    unsigned u; asm("cvt.rna.tf32.f32 %0, %1;" : "=r"(u) : "f"(v)); return u;
}

__global__ __launch_bounds__(NT_, 2)
void guide_mma_kernel(const float* __restrict__ z_pres,
                      const float* __restrict__ z_what,
                      const float* __restrict__ z_where,
                      const float* __restrict__ sigma_p,
                      const float* __restrict__ slope_strk_p,
                      const float* __restrict__ slope_p,
                      float* __restrict__ out)
{
    __shared__ float2 curve[KPAD_];          // (cx, cy) per t
    __shared__ float  part[NW_ * PWARP_];    // per-warp C partials (32x34)
    __shared__ float  red[8];
    __shared__ unsigned int slast;

    const int bk   = blockIdx.x;             // 0..255 = b*4 + k
    const int tid  = threadIdx.x;
    const int wid  = tid >> 5;
    const int lane = tid & 31;
    const int gr   = lane >> 2;              // groupID 0..7
    const int tc   = lane & 3;               // thread-in-group 0..3

    // ---- transform params (uniform) ----
    const float s   = z_where[bk * 3 + 0];
    const float sh0 = z_where[bk * 3 + 1];
    const float sh1 = z_where[bk * 3 + 2];

    float px0, px1, px2, px3, px4, py0, py1, py2, py3, py4;
    {
        const float* w = z_what + bk * PTS_ * 2;
        px0 = w[0] * s + sh0;  py0 = w[1] * s + sh1;
        px1 = w[2] * s + sh0;  py1 = w[3] * s + sh1;
        px2 = w[4] * s + sh0;  py2 = w[5] * s + sh1;
        px3 = w[6] * s + sh0;  py3 = w[7] * s + sh1;
        px4 = w[8] * s + sh0;  py4 = w[9] * s + sh1;
    }
    const float sigma = *sigma_p;
    const float ninv  = -1.0f / (2.0f * sigma * sigma);

    // ---- precompute curve (cx,cy) for all padded t ----
    for (int k = tid; k < KPAD_; k += NT_) {
        float cx = 1e9f, cy = 1e9f;
        if (k < STEPS_) {
            const float u  = (float)k * (1.0f / (float)(STEPS_ - 1));
            const float v  = 1.0f - u;
            const float u2 = u * u, v2 = v * v;
            const float b0 = v2 * v2;
            const float b1 = 4.0f * u * (v * v2);
            const float b2 = 6.0f * u2 * v2;
            const float b3 = 4.0f * (u2 * u) * v;
            const float b4 = u2 * u2;
            cx = b0*px0 + b1*px1 + b2*px2 + b3*px3 + b4*px4;
            cy = b0*py0 + b1*py1 + b2*py2 + b3*py3 + b4*py4;
        }
        curve[k] = make_float2(cx, cy);
    }
    __syncthreads();

    // per-lane grid values for rows/cols {gr, gr+8, gr+16, gr+24}
    float gv[4];
    gv[0] = (float)gr        * (1.0f / 27.0f);
    gv[1] = (float)(gr + 8)  * (1.0f / 27.0f);
    gv[2] = (float)(gr + 16) * (1.0f / 27.0f);
    gv[3] = (gr < 4) ? (float)(gr + 24) * (1.0f / 27.0f) : 1e6f;

    // accumulators: D[mt][nt][4]
    float D[2][4][4];
#pragma unroll
    for (int mt = 0; mt < 2; mt++)
#pragma unroll
        for (int nt = 0; nt < 4; nt++)
#pragma unroll
            for (int r = 0; r < 4; r++) D[mt][nt][r] = 0.0f;

    // ---- main k-split MMA loop: warp wid owns ksteps [wid*8, min(+8,63)) ----
    const int ks0 = wid * 8;
    const int ks1 = (ks0 + 8 < KSTEPS_) ? ks0 + 8 : KSTEPS_;
#pragma unroll 1
    for (int ks = ks0; ks < ks1; ks++) {
        const int kA = ks * 8 + tc;
        const float2 cA = curve[kA];
        const float2 cB = curve[kA + 4];

        // 16 exps: ey[r][kk] (A operands), ex[r][kk] (B operands)
        float ey[4][2], ex[4][2];
#pragma unroll
        for (int r = 0; r < 4; r++) {
            float d0 = gv[r] - cA.y;  ey[r][0] = __expf(d0 * d0 * ninv);
            float d1 = gv[r] - cB.y;  ey[r][1] = __expf(d1 * d1 * ninv);
            float d2 = gv[r] - cA.x;  ex[r][0] = __expf(d2 * d2 * ninv);
            float d3 = gv[r] - cB.x;  ex[r][1] = __expf(d3 * d3 * ninv);
        }

        // tf32 split: big (tf32-exact) + small (residual)
        unsigned eyb[4][2], exb[4][2], eys[4][2], exs[4][2];
#pragma unroll
        for (int r = 0; r < 4; r++)
#pragma unroll
            for (int kk = 0; kk < 2; kk++) {
                unsigned b1_ = tf32_big(ey[r][kk]);
                eyb[r][kk] = b1_;
                eys[r][kk] = __float_as_uint(ey[r][kk] - __uint_as_float(b1_));
                unsigned b2_ = tf32_big(ex[r][kk]);
                exb[r][kk] = b2_;
                exs[r][kk] = __float_as_uint(ex[r][kk] - __uint_as_float(b2_));
            }

        // 8 tiles x 3 MMAs (3xTF32)
#pragma unroll
        for (int mt = 0; mt < 2; mt++) {
            const unsigned ab0 = eyb[2*mt][0], ab1 = eyb[2*mt+1][0];
            const unsigned ab2 = eyb[2*mt][1], ab3 = eyb[2*mt+1][1];
            const unsigned as0 = eys[2*mt][0], as1 = eys[2*mt+1][0];
            const unsigned as2 = eys[2*mt][1], as3 = eys[2*mt+1][1];
#pragma unroll
            for (int nt = 0; nt < 4; nt++) {
                const unsigned bb0 = exb[nt][0], bb1 = exb[nt][1];
                const unsigned bs0 = exs[nt][0], bs1 = exs[nt][1];
                mma_tf32(D[mt][nt], ab0, ab1, ab2, ab3, bb0, bb1);
                mma_tf32(D[mt][nt], ab0, ab1, ab2, ab3, bs0, bs1);
                mma_tf32(D[mt][nt], as0, as1, as2, as3, bb0, bb1);
            }
        }
    }

    // ---- store per-warp C partial to smem ----
    {
        float* wp = part + wid * PWARP_;
#pragma unroll
        for (int mt = 0; mt < 2; mt++)
#pragma unroll
            for (int nt = 0; nt < 4; nt++) {
                const int row = mt * 16 + gr;
                const int col = nt * 8 + 2 * tc;
                float* b0 = wp + row * PSTR_ + col;
                b0[0] = D[mt][nt][0];
                b0[1] = D[mt][nt][1];
                b0[8 * PSTR_]     = D[mt][nt][2];
                b0[8 * PSTR_ + 1] = D[mt][nt][3];
            }
    }
    __syncthreads();

    // ---- epilogue: sum warps, z_pres scale, maxnorm, tanh-norm, stage ----
    const float zp = z_pres[bk];
    float myv[4];
    float lmax = 0.0f;
#pragma unroll
    for (int r = 0; r < 4; r++) {
        const int p = r * NT_ + tid;
        float v = 0.0f;
        if (p < PIX_) {
            const int y = p / RES_;
            const int x = p - y * RES_;
            const int o = y * PSTR_ + x;
            v = part[o];
#pragma unroll
            for (int w = 1; w < NW_; w++) v += part[w * PWARP_ + o];
            v *= zp;
        }
        myv[r] = v;
        lmax = fmaxf(lmax, v);
    }
#pragma unroll
    for (int o = 16; o > 0; o >>= 1)
        lmax = fmaxf(lmax, __shfl_xor_sync(0xffffffffu, lmax, o));
    if ((tid & 31) == 0) red[tid >> 5] = lmax;
    __syncthreads();
    float bmax = red[0];
#pragma unroll
    for (int w = 1; w < 8; w++) bmax = fmaxf(bmax, red[w]);

    const float scale = 1.0f / (bmax + 1e-6f);
    const float sl    = *slope_strk_p;
    const float itsl  = 1.0f / tanhf(sl);
    float* stage = g_stage + bk * PIX_;
#pragma unroll
    for (int r = 0; r < 4; r++) {
        const int p = r * NT_ + tid;
        if (p < PIX_)
            stage[p] = tanhf(myv[r] * scale * sl) * itsl;
    }

    // ---- fused compose: last CTA of each batch composes the image ----
    if (tid == 0) {
        __threadfence();   // publish stage writes before arrival
        unsigned int old = atomicAdd(&g_cnt[bk >> 2], 1u);
        slast = (old == 3u) ? 1u : 0u;
    }
    __syncthreads();
    if (slast) {
        __threadfence();   // acquire: see peer CTAs' stage writes
        const int b = bk >> 2;
        const float* st = g_stage + b * KK_ * PIX_;
        const float sl2 = *slope_p;
        const float it2 = 1.0f / tanhf(sl2);
        for (int p = tid; p < PIX_; p += NT_) {
            const float ssum = st[p] + st[PIX_ + p] + st[2*PIX_ + p] + st[3*PIX_ + p];
            out[b * PIX_ + p] = tanhf(ssum * sl2) * it2;
        }
        if (tid == 0) g_cnt[b] = 0u;   // reset for next (graph-replayed) call
    }
}

extern "C" void kernel_launch(void* const* d_in, const int* in_sizes, int n_in,
                              void* d_out, int out_size)
{
    const float* z_pres     = (const float*)d_in[0];
    const float* z_what     = (const float*)d_in[1];
    const float* z_where    = (const float*)d_in[2];
    const float* sigma      = (const float*)d_in[3];
    const float* slope_strk = (const float*)d_in[4];
    const float* slope      = (const float*)d_in[5];
    float* out = (float*)d_out;

    guide_mma_kernel<<<BS_ * KK_, NT_>>>(z_pres, z_what, z_where,
                                         sigma, slope_strk, slope, out);
}

// round 8
// speedup vs baseline: 2.1850x; 1.3375x over previous
#include <cuda_runtime.h>
#include <math.h>

#define BS_    64
#define KK_    4
#define PTS_   5
#define RES_   28
#define STEPS_ 500
#define NT_    256
#define NW_    8            // warps per CTA
#define KSTEPS_ 63          // ceil(504/8)
#define KPAD_  504
#define PIX_ (RES_*RES_)    // 784
#define PSTR_ 34            // padded row stride of C partial
#define PWARP_ (32*PSTR_)   // 1088 floats per warp partial

// staging: tanh-normed strokes per (b,k)
__device__ float g_stage[BS_ * KK_ * PIX_];
// per-batch arrival counters for fused compose (zero-init; reset each run)
__device__ unsigned int g_cnt[BS_];

__device__ __forceinline__ void mma_tf32(float* d,
                                         unsigned a0, unsigned a1, unsigned a2, unsigned a3,
                                         unsigned b0, unsigned b1) {
    asm volatile(
        "mma.sync.aligned.m16n8k8.row.col.f32.tf32.tf32.f32 "
        "{%0,%1,%2,%3}, {%4,%5,%6,%7}, {%8,%9}, {%0,%1,%2,%3};"
        : "+f"(d[0]), "+f"(d[1]), "+f"(d[2]), "+f"(d[3])
        : "r"(a0), "r"(a1), "r"(a2), "r"(a3), "r"(b0), "r"(b1));
}
__device__ __forceinline__ unsigned tf32_big(float v) {
    unsigned u; asm("cvt.rna.tf32.f32 %0, %1;" : "=r"(u) : "f"(v)); return u;
}
__device__ __forceinline__ float ex2f(float x) {
    float r; asm("ex2.approx.ftz.f32 %0, %1;" : "=f"(r) : "f"(x)); return r;
}

__global__ __launch_bounds__(NT_, 2)
void guide_mma_kernel(const float* __restrict__ z_pres,
                      const float* __restrict__ z_what,
                      const float* __restrict__ z_where,
                      const float* __restrict__ sigma_p,
                      const float* __restrict__ slope_strk_p,
                      const float* __restrict__ slope_p,
                      float* __restrict__ out)
{
    __shared__ float2 curve[KPAD_];          // (cx, cy) per t
    __shared__ float  part[NW_ * PWARP_];    // per-warp C partials (32x34)
    __shared__ float  red[8];
    __shared__ unsigned int slast;

    const int bk   = blockIdx.x;             // 0..255 = b*4 + k
    const int tid  = threadIdx.x;
    const int wid  = tid >> 5;
    const int lane = tid & 31;
    const int gr   = lane >> 2;              // groupID 0..7
    const int tc   = lane & 3;               // thread-in-group 0..3

    // ---- transform params (uniform) ----
    const float s   = z_where[bk * 3 + 0];
    const float sh0 = z_where[bk * 3 + 1];
    const float sh1 = z_where[bk * 3 + 2];

    float px0, px1, px2, px3, px4, py0, py1, py2, py3, py4;
    {
        const float* w = z_what + bk * PTS_ * 2;
        px0 = w[0] * s + sh0;  py0 = w[1] * s + sh1;
        px1 = w[2] * s + sh0;  py1 = w[3] * s + sh1;
        px2 = w[4] * s + sh0;  py2 = w[5] * s + sh1;
        px3 = w[6] * s + sh0;  py3 = w[7] * s + sh1;
        px4 = w[8] * s + sh0;  py4 = w[9] * s + sh1;
    }
    const float sigma = *sigma_p;
    // fold log2(e) so exp(-d^2*inv) == ex2(d^2 * ninv2)
    const float ninv2 = (-1.0f / (2.0f * sigma * sigma)) * 1.44269504088896f;

    // ---- precompute curve (cx,cy) for all padded t ----
    for (int k = tid; k < KPAD_; k += NT_) {
        float cx = 1e9f, cy = 1e9f;
        if (k < STEPS_) {
            const float u  = (float)k * (1.0f / (float)(STEPS_ - 1));
            const float v  = 1.0f - u;
            const float u2 = u * u, v2 = v * v;
            const float b0 = v2 * v2;
            const float b1 = 4.0f * u * (v * v2);
            const float b2 = 6.0f * u2 * v2;
            const float b3 = 4.0f * (u2 * u) * v;
            const float b4 = u2 * u2;
            cx = b0*px0 + b1*px1 + b2*px2 + b3*px3 + b4*px4;
            cy = b0*py0 + b1*py1 + b2*py2 + b3*py3 + b4*py4;
        }
        curve[k] = make_float2(cx, cy);
    }
    __syncthreads();

    // per-lane grid values for rows/cols {gr, gr+8, gr+16, gr+24}
    float gv[4];
    gv[0] = (float)gr        * (1.0f / 27.0f);
    gv[1] = (float)(gr + 8)  * (1.0f / 27.0f);
    gv[2] = (float)(gr + 16) * (1.0f / 27.0f);
    gv[3] = (gr < 4) ? (float)(gr + 24) * (1.0f / 27.0f) : 1e6f;

    // accumulators: D[mt][nt][4]
    float D[2][4][4];
#pragma unroll
    for (int mt = 0; mt < 2; mt++)
#pragma unroll
        for (int nt = 0; nt < 4; nt++)
#pragma unroll
            for (int r = 0; r < 4; r++) D[mt][nt][r] = 0.0f;

    // ---- main k-split MMA loop: warp wid owns ksteps [wid*8, min(+8,63)) ----
    const int ks0 = wid * 8;
    const int ks1 = (ks0 + 8 < KSTEPS_) ? ks0 + 8 : KSTEPS_;
    const float2* cp = curve + ks0 * 8 + tc;
#pragma unroll 1
    for (int ks = ks0; ks < ks1; ks++) {
        const float2 cA = cp[0];
        const float2 cB = cp[4];
        cp += 8;

        // 16 exps: ey[r][kk] (A operands), ex[r][kk] (B operands)
        float ey[4][2], ex[4][2];
#pragma unroll
        for (int r = 0; r < 4; r++) {
            float d0 = gv[r] - cA.y;  ey[r][0] = ex2f(d0 * d0 * ninv2);
            float d1 = gv[r] - cB.y;  ey[r][1] = ex2f(d1 * d1 * ninv2);
            float d2 = gv[r] - cA.x;  ex[r][0] = ex2f(d2 * d2 * ninv2);
            float d3 = gv[r] - cB.x;  ex[r][1] = ex2f(d3 * d3 * ninv2);
        }

        // A-side split (exact sum), B-side plain tf32
        unsigned eyb[4][2], eys[4][2], exb[4][2];
#pragma unroll
        for (int r = 0; r < 4; r++)
#pragma unroll
            for (int kk = 0; kk < 2; kk++) {
                unsigned b1_ = tf32_big(ey[r][kk]);
                eyb[r][kk] = b1_;
                eys[r][kk] = __float_as_uint(ey[r][kk] - __uint_as_float(b1_));
                exb[r][kk] = tf32_big(ex[r][kk]);
            }

        // 8 tiles x 2 MMAs
#pragma unroll
        for (int mt = 0; mt < 2; mt++) {
            const unsigned ab0 = eyb[2*mt][0], ab1 = eyb[2*mt+1][0];
            const unsigned ab2 = eyb[2*mt][1], ab3 = eyb[2*mt+1][1];
            const unsigned as0 = eys[2*mt][0], as1 = eys[2*mt+1][0];
            const unsigned as2 = eys[2*mt][1], as3 = eys[2*mt+1][1];
#pragma unroll
            for (int nt = 0; nt < 4; nt++) {
                const unsigned bb0 = exb[nt][0], bb1 = exb[nt][1];
                mma_tf32(D[mt][nt], ab0, ab1, ab2, ab3, bb0, bb1);
                mma_tf32(D[mt][nt], as0, as1, as2, as3, bb0, bb1);
            }
        }
    }

    // ---- store per-warp C partial to smem ----
    {
        float* wp = part + wid * PWARP_;
#pragma unroll
        for (int mt = 0; mt < 2; mt++)
#pragma unroll
            for (int nt = 0; nt < 4; nt++) {
                const int row = mt * 16 + gr;
                const int col = nt * 8 + 2 * tc;
                float* b0 = wp + row * PSTR_ + col;
                b0[0] = D[mt][nt][0];
                b0[1] = D[mt][nt][1];
                b0[8 * PSTR_]     = D[mt][nt][2];
                b0[8 * PSTR_ + 1] = D[mt][nt][3];
            }
    }
    __syncthreads();

    // ---- epilogue: sum warps, z_pres scale, maxnorm, tanh-norm, stage ----
    const float zp = z_pres[bk];
    float myv[4];
    float lmax = 0.0f;
#pragma unroll
    for (int r = 0; r < 4; r++) {
        const int p = r * NT_ + tid;
        float v = 0.0f;
        if (p < PIX_) {
            const int y = p / RES_;
            const int x = p - y * RES_;
            const int o = y * PSTR_ + x;
            v = part[o];
#pragma unroll
            for (int w = 1; w < NW_; w++) v += part[w * PWARP_ + o];
            v *= zp;
        }
        myv[r] = v;
        lmax = fmaxf(lmax, v);
    }
#pragma unroll
    for (int o = 16; o > 0; o >>= 1)
        lmax = fmaxf(lmax, __shfl_xor_sync(0xffffffffu, lmax, o));
    if ((tid & 31) == 0) red[tid >> 5] = lmax;
    __syncthreads();
    float bmax = red[0];
#pragma unroll
    for (int w = 1; w < 8; w++) bmax = fmaxf(bmax, red[w]);

    const float scale = 1.0f / (bmax + 1e-6f);
    const float sl    = *slope_strk_p;
    const float itsl  = 1.0f / tanhf(sl);
    float* stage = g_stage + bk * PIX_;
#pragma unroll
    for (int r = 0; r < 4; r++) {
        const int p = r * NT_ + tid;
        if (p < PIX_)
            stage[p] = tanhf(myv[r] * scale * sl) * itsl;
    }

    // ---- fused compose: last CTA of each batch composes the image ----
    if (tid == 0) {
        __threadfence();   // publish stage writes before arrival
        unsigned int old = atomicAdd(&g_cnt[bk >> 2], 1u);
        slast = (old == 3u) ? 1u : 0u;
    }
    __syncthreads();
    if (slast) {
        __threadfence();   // acquire: see peer CTAs' stage writes
        const int b = bk >> 2;
        const float* st = g_stage + b * KK_ * PIX_;
        const float sl2 = *slope_p;
        const float it2 = 1.0f / tanhf(sl2);
        for (int p = tid; p < PIX_; p += NT_) {
            const float ssum = st[p] + st[PIX_ + p] + st[2*PIX_ + p] + st[3*PIX_ + p];
            out[b * PIX_ + p] = tanhf(ssum * sl2) * it2;
        }
        if (tid == 0) g_cnt[b] = 0u;   // reset for next (graph-replayed) call
    }
}

extern "C" void kernel_launch(void* const* d_in, const int* in_sizes, int n_in,
                              void* d_out, int out_size)
{
    const float* z_pres     = (const float*)d_in[0];
    const float* z_what     = (const float*)d_in[1];
    const float* z_where    = (const float*)d_in[2];
    const float* sigma      = (const float*)d_in[3];
    const float* slope_strk = (const float*)d_in[4];
    const float* slope      = (const float*)d_in[5];
    float* out = (float*)d_out;

    guide_mma_kernel<<<BS_ * KK_, NT_>>>(z_pres, z_what, z_where,
                                         sigma, slope_strk, slope, out);
}